// round 1
// baseline (speedup 1.0000x reference)
#include <cuda_runtime.h>
#include <cstdint>
#include <math.h>

// Problem dims
#define BB 64
#define TT 4096
#define HH 256
#define II 7
#define XD 12   // I + F

// ---------------- device scratch (allocation-free rule: __device__ globals) ---
__device__ float g_ht[(size_t)BB * TT * HH];   // 256 MB: RNN hidden states
__device__ float g_wt[110520];                 // transposed MLP weights

// MLP layer dims
// L0 256x261, L1 128x256, L2 64x128, L3 32x64, L4 16x32, L5 8x16, L6 7x8
#define OFF0 0
#define OFF1 66816
#define OFF2 99584
#define OFF3 107776
#define OFF4 109824
#define OFF5 110336
#define OFF6 110464

// ---------------- f32x2 helpers ----------------------------------------------
__device__ __forceinline__ unsigned long long fma2(unsigned long long a,
                                                   unsigned long long b,
                                                   unsigned long long c) {
    unsigned long long d;
    asm("fma.rn.f32x2 %0, %1, %2, %3;" : "=l"(d) : "l"(a), "l"(b), "l"(c));
    return d;
}
__device__ __forceinline__ unsigned long long pack2(float lo, float hi) {
    unsigned long long d;
    asm("mov.b64 %0, {%1, %2};" : "=l"(d) : "f"(lo), "f"(hi));
    return d;
}
__device__ __forceinline__ float2 unpack2(unsigned long long v) {
    float lo, hi;
    asm("mov.b64 {%0, %1}, %2;" : "=f"(lo), "=f"(hi) : "l"(v));
    return make_float2(lo, hi);
}

// ---------------- RNN kernel ---------------------------------------------------
// One CTA per batch chain. Thread j owns output h[j].
// W_hh row j: cols [0,160) in registers (80 f32x2 pairs), cols [160,256) in smem.
#define REGP 80          // register pairs (160 floats)
#define SWC  96          // smem weight cols per row
#define SWS  100         // padded smem row stride (conflict-free for LDS.128)
#define XCH  512         // x staging chunk (steps)

#define RNN_SMF (256*SWS + XCH*XD + 2*HH)      // floats
#define RNN_SMEM (RNN_SMF * 4)

__global__ __launch_bounds__(256, 1) void rnn_kernel(
    const float* __restrict__ x, const float* __restrict__ W_ih,
    const float* __restrict__ W_hh, const float* __restrict__ b_ih,
    const float* __restrict__ b_hh, float* __restrict__ out)
{
    extern __shared__ float sm[];
    float* ws = sm;                       // 256*SWS
    float* xs = sm + 256 * SWS;           // XCH*XD
    float* hb = sm + 256 * SWS + XCH * XD; // 2*HH double buffer
    const int j = threadIdx.x;
    const int b = blockIdx.x;

    // register-resident weights (row j, cols 0..159 as 80 pairs)
    unsigned long long w2[REGP];
    {
        const unsigned long long* wrow =
            (const unsigned long long*)(W_hh + (size_t)j * HH);
        #pragma unroll
        for (int p = 0; p < REGP; p++) w2[p] = wrow[p];
    }

    // smem-resident weights (cols 160..255), coalesced load
    for (int idx = j; idx < 256 * SWC; idx += 256) {
        int r = idx / SWC, c = idx - r * SWC;
        ws[r * SWS + c] = W_hh[r * HH + 2 * REGP + c];
    }

    float wih[II];
    #pragma unroll
    for (int i = 0; i < II; i++) wih[i] = W_ih[j * II + i];
    const float bias = b_ih[j] + b_hh[j];

    hb[j] = 0.0f;
    hb[HH + j] = 0.0f;
    __syncthreads();

    const float4* xg = (const float4*)(x + (size_t)b * TT * XD);
    float* hout = g_ht + (size_t)b * TT * HH;
    const ulonglong2* wsr = (const ulonglong2*)(ws + j * SWS);

    int buf = 0;
    float hlast = 0.0f;
    for (int t = 0; t < TT; t++) {
        const int tl = t & (XCH - 1);
        if (tl == 0) {
            // stage next x chunk (XCH steps * 12 floats = XCH*3 float4)
            const int base = t * 3;
            float4* xs4 = (float4*)xs;
            for (int idx = j; idx < XCH * 3; idx += 256)
                xs4[idx] = xg[base + idx];
            __syncthreads();
        }
        const float4* xr = (const float4*)(xs + tl * XD);
        const float4 xa = xr[0];
        const float4 xb = xr[1];
        float xw = bias;
        xw = fmaf(xa.x, wih[0], xw);
        xw = fmaf(xa.y, wih[1], xw);
        xw = fmaf(xa.z, wih[2], xw);
        xw = fmaf(xa.w, wih[3], xw);
        xw = fmaf(xb.x, wih[4], xw);
        xw = fmaf(xb.y, wih[5], xw);
        xw = fmaf(xb.z, wih[6], xw);

        unsigned long long acc0 = pack2(xw, 0.0f);
        unsigned long long acc1 = pack2(0.0f, 0.0f);
        const ulonglong2* h2 = (const ulonglong2*)(hb + buf * HH);

        #pragma unroll
        for (int q = 0; q < REGP / 2; q++) {          // k = 0..159
            ulonglong2 u = h2[q];
            acc0 = fma2(w2[2 * q],     u.x, acc0);
            acc1 = fma2(w2[2 * q + 1], u.y, acc1);
        }
        #pragma unroll
        for (int r = 0; r < SWC / 4; r++) {           // k = 160..255
            ulonglong2 u = h2[REGP / 2 + r];
            ulonglong2 wv = wsr[r];
            acc0 = fma2(wv.x, u.x, acc0);
            acc1 = fma2(wv.y, u.y, acc1);
        }
        float2 a = unpack2(acc0), c = unpack2(acc1);
        float s = (a.x + a.y) + (c.x + c.y);
        float hn = tanhf(s);

        hb[(buf ^ 1) * HH + j] = hn;
        hout[(size_t)t * HH + j] = hn;
        hlast = hn;
        __syncthreads();
        buf ^= 1;
    }
    // h_last output lives after ot: offset B*T*7
    out[(size_t)BB * TT * II + (size_t)b * HH + j] = hlast;
}

// ---------------- MLP kernel ---------------------------------------------------
// 32 tokens per CTA, activations transposed [k][tok] in smem, f32x2 over token
// pairs, transposed weights streamed from L2.
#define TOKP 36   // padded token stride (conflict-free)
#define MLP_SMF (264 * TOKP + 256 * TOKP)
#define MLP_SMEM (MLP_SMF * 4)

template<int DOUT, int DIN, int TPG, bool LEAKY>
__device__ __forceinline__ void mlp_layer(const float* __restrict__ zin,
                                          float* __restrict__ zout,
                                          const float* __restrict__ wt,
                                          const float* __restrict__ bias)
{
    const int tid = threadIdx.x;
    const int o = tid % DOUT;
    const int g = tid / DOUT;

    if constexpr (TPG >= 4) {
        constexpr int NP = TPG / 2;
        unsigned long long acc[NP];
        #pragma unroll
        for (int p = 0; p < NP; p++) acc[p] = pack2(0.0f, 0.0f);
        #pragma unroll 4
        for (int k = 0; k < DIN; k++) {
            const float w = wt[k * DOUT + o];
            const unsigned long long w2 = pack2(w, w);
            const ulonglong2* zr = (const ulonglong2*)(zin + k * TOKP + g * TPG);
            #pragma unroll
            for (int p = 0; p < TPG / 4; p++) {
                ulonglong2 u = zr[p];
                acc[2 * p]     = fma2(w2, u.x, acc[2 * p]);
                acc[2 * p + 1] = fma2(w2, u.y, acc[2 * p + 1]);
            }
        }
        const float bv = bias[o];
        float* orow = zout + o * TOKP + g * TPG;
        #pragma unroll
        for (int p = 0; p < NP; p++) {
            float2 v = unpack2(acc[p]);
            v.x += bv; v.y += bv;
            if (LEAKY) { v.x = fmaxf(v.x, 0.01f * v.x); v.y = fmaxf(v.y, 0.01f * v.y); }
            orow[2 * p] = v.x; orow[2 * p + 1] = v.y;
        }
    } else if constexpr (TPG == 2) {
        unsigned long long acc = pack2(0.0f, 0.0f);
        #pragma unroll 4
        for (int k = 0; k < DIN; k++) {
            const float w = wt[k * DOUT + o];
            unsigned long long u = *(const unsigned long long*)(zin + k * TOKP + g * 2);
            acc = fma2(pack2(w, w), u, acc);
        }
        const float bv = bias[o];
        float2 v = unpack2(acc);
        v.x += bv; v.y += bv;
        if (LEAKY) { v.x = fmaxf(v.x, 0.01f * v.x); v.y = fmaxf(v.y, 0.01f * v.y); }
        float* orow = zout + o * TOKP + g * 2;
        orow[0] = v.x; orow[1] = v.y;
    } else {
        float acc = 0.0f;
        #pragma unroll 4
        for (int k = 0; k < DIN; k++)
            acc = fmaf(wt[k * DOUT + o], zin[k * TOKP + g], acc);
        float v = acc + bias[o];
        if (LEAKY) v = fmaxf(v, 0.01f * v);
        zout[o * TOKP + g] = v;
    }
}

__global__ __launch_bounds__(256) void mlp_kernel(
    const float* __restrict__ x,
    const float* __restrict__ b0, const float* __restrict__ b1,
    const float* __restrict__ b2, const float* __restrict__ b3,
    const float* __restrict__ b4, const float* __restrict__ b5,
    const float* __restrict__ b6, float* __restrict__ out)
{
    extern __shared__ float sm[];
    float* bufA = sm;               // up to 264 rows * TOKP
    float* bufB = sm + 264 * TOKP;  // up to 256 rows * TOKP
    const int tid = threadIdx.x;
    const size_t tok0 = (size_t)blockIdx.x * 32;

    // load ht (transposed) rows 0..255
    for (int idx = tid; idx < 32 * 256; idx += 256) {
        const int tk = idx >> 8, jj = idx & 255;
        bufA[jj * TOKP + tk] = g_ht[(tok0 + tk) * HH + jj];
    }
    // x_fixed rows 256..260
    for (int idx = tid; idx < 32 * 5; idx += 256) {
        const int tk = idx / 5, i = idx - tk * 5;
        bufA[(256 + i) * TOKP + tk] = x[(tok0 + tk) * XD + II + i];
    }
    __syncthreads();

    mlp_layer<256, 261, 32, true>(bufA, bufB, g_wt + OFF0, b0); __syncthreads();
    mlp_layer<128, 256, 16, true>(bufB, bufA, g_wt + OFF1, b1); __syncthreads();
    mlp_layer< 64, 128,  8, true>(bufA, bufB, g_wt + OFF2, b2); __syncthreads();
    mlp_layer< 32,  64,  4, true>(bufB, bufA, g_wt + OFF3, b3); __syncthreads();
    mlp_layer< 16,  32,  2, true>(bufA, bufB, g_wt + OFF4, b4); __syncthreads();
    mlp_layer<  8,  16,  1, true>(bufB, bufA, g_wt + OFF5, b5); __syncthreads();

    // final linear 8 -> 7 straight to gmem
    {
        const int o = tid & 7, g = tid >> 3;   // g in [0,32)
        if (o < 7) {
            float acc = b6[o];
            #pragma unroll
            for (int k = 0; k < 8; k++)
                acc = fmaf(g_wt[OFF6 + k * 7 + o], bufA[k * TOKP + g], acc);
            out[(tok0 + g) * II + o] = acc;
        }
    }
}

// ---------------- weight transpose prep ---------------------------------------
__global__ void prep_kernel(const float* __restrict__ W0, const float* __restrict__ W1,
                            const float* __restrict__ W2, const float* __restrict__ W3,
                            const float* __restrict__ W4, const float* __restrict__ W5,
                            const float* __restrict__ W6)
{
    const float* Ws[7] = {W0, W1, W2, W3, W4, W5, W6};
    const int douts[7] = {256, 128, 64, 32, 16, 8, 7};
    const int dins[7]  = {261, 256, 128, 64, 32, 16, 8};
    int off = 0;
    const int stride = gridDim.x * blockDim.x;
    const int tid0 = blockIdx.x * blockDim.x + threadIdx.x;
    for (int l = 0; l < 7; l++) {
        const int dout = douts[l], din = dins[l], n = dout * din;
        const float* W = Ws[l];
        for (int idx = tid0; idx < n; idx += stride) {
            const int k = idx / dout, o = idx - k * dout;
            g_wt[off + idx] = W[o * din + k];
        }
        off += n;
    }
}

// ---------------- launch -------------------------------------------------------
extern "C" void kernel_launch(void* const* d_in, const int* in_sizes, int n_in,
                              void* d_out, int out_size)
{
    const float* x    = (const float*)d_in[0];
    const float* W_ih = (const float*)d_in[1];
    const float* W_hh = (const float*)d_in[2];
    const float* b_ih = (const float*)d_in[3];
    const float* b_hh = (const float*)d_in[4];
    const float* W[7];
    const float* bb[7];
    for (int i = 0; i < 7; i++) {
        W[i]  = (const float*)d_in[5 + 2 * i];
        bb[i] = (const float*)d_in[6 + 2 * i];
    }
    float* out = (float*)d_out;

    cudaFuncSetAttribute(rnn_kernel, cudaFuncAttributeMaxDynamicSharedMemorySize, RNN_SMEM);
    cudaFuncSetAttribute(mlp_kernel, cudaFuncAttributeMaxDynamicSharedMemorySize, MLP_SMEM);

    prep_kernel<<<64, 256>>>(W[0], W[1], W[2], W[3], W[4], W[5], W[6]);
    rnn_kernel<<<BB, 256, RNN_SMEM>>>(x, W_ih, W_hh, b_ih, b_hh, out);
    mlp_kernel<<<(BB * TT) / 32, 256, MLP_SMEM>>>(x, bb[0], bb[1], bb[2], bb[3],
                                                  bb[4], bb[5], bb[6], out);
}

// round 2
// speedup vs baseline: 1.1143x; 1.1143x over previous
#include <cuda_runtime.h>
#include <cstdint>
#include <math.h>

// Problem dims
#define BB 64
#define TT 4096
#define HH 256
#define II 7
#define XD 12   // I + F

#define NRNN 64
#define NWORK 84
#define NCTA (NRNN + NWORK)

// ---------------- device scratch ----------------------------------------------
__device__ float g_ht[(size_t)BB * TT * HH];   // RNN hidden states
__device__ float g_wt[110520];                 // transposed MLP weights
__device__ int   g_prog[BB];                   // RNN progress (steps done) per chain

// MLP layer offsets in g_wt
#define OFF0 0
#define OFF1 66816
#define OFF2 99584
#define OFF3 107776
#define OFF4 109824
#define OFF5 110336
#define OFF6 110464

// ---------------- f32x2 helpers ----------------------------------------------
__device__ __forceinline__ unsigned long long fma2(unsigned long long a,
                                                   unsigned long long b,
                                                   unsigned long long c) {
    unsigned long long d;
    asm("fma.rn.f32x2 %0, %1, %2, %3;" : "=l"(d) : "l"(a), "l"(b), "l"(c));
    return d;
}
__device__ __forceinline__ unsigned long long pack2(float lo, float hi) {
    unsigned long long d;
    asm("mov.b64 %0, {%1, %2};" : "=l"(d) : "f"(lo), "f"(hi));
    return d;
}
__device__ __forceinline__ float2 unpack2(unsigned long long v) {
    float lo, hi;
    asm("mov.b64 {%0, %1}, %2;" : "=f"(lo), "=f"(hi) : "l"(v));
    return make_float2(lo, hi);
}
__device__ __forceinline__ int ld_acquire(const int* p) {
    int v;
    asm volatile("ld.global.acquire.gpu.b32 %0, [%1];" : "=r"(v) : "l"(p));
    return v;
}
__device__ __forceinline__ void st_release(int* p, int v) {
    asm volatile("st.global.release.gpu.b32 [%0], %1;" :: "l"(p), "r"(v));
}

// ---------------- RNN config ---------------------------------------------------
// 256 threads. tid -> (jj = tid>>1 in [0,128), half = tid&1).
// Thread computes partial dots for outputs {jj, jj+128} over k in [half*128, half*128+128).
// Per output row: RP=84 weight floats in registers (42 ull), 44 floats in smem.
#define RP   84
#define WST  92      // per-thread smem weight stride (floats), 23*16B -> conflict-free
#define XCH  512     // x staging chunk (steps)
#define HBS  264     // h buffer stride (floats): [0,128) half0, pad, [132,260) half1

#define RNN_SMF (256 * WST + XCH * XD + 2 * HBS)
#define FUSED_SMEM_B (RNN_SMF * 4)   // 120,896 B > MLP's 74,880 B

// ---------------- MLP layer (unchanged from round 1) ---------------------------
#define TOKP 36

template<int DOUT, int DIN, int TPG, bool LEAKY>
__device__ __forceinline__ void mlp_layer(const float* __restrict__ zin,
                                          float* __restrict__ zout,
                                          const float* __restrict__ wt,
                                          const float* __restrict__ bias)
{
    const int tid = threadIdx.x;
    const int o = tid % DOUT;
    const int g = tid / DOUT;

    if constexpr (TPG >= 4) {
        constexpr int NP = TPG / 2;
        unsigned long long acc[NP];
        #pragma unroll
        for (int p = 0; p < NP; p++) acc[p] = pack2(0.0f, 0.0f);
        #pragma unroll 4
        for (int k = 0; k < DIN; k++) {
            const float w = wt[k * DOUT + o];
            const unsigned long long w2 = pack2(w, w);
            const ulonglong2* zr = (const ulonglong2*)(zin + k * TOKP + g * TPG);
            #pragma unroll
            for (int p = 0; p < TPG / 4; p++) {
                ulonglong2 u = zr[p];
                acc[2 * p]     = fma2(w2, u.x, acc[2 * p]);
                acc[2 * p + 1] = fma2(w2, u.y, acc[2 * p + 1]);
            }
        }
        const float bv = bias[o];
        float* orow = zout + o * TOKP + g * TPG;
        #pragma unroll
        for (int p = 0; p < NP; p++) {
            float2 v = unpack2(acc[p]);
            v.x += bv; v.y += bv;
            if (LEAKY) { v.x = fmaxf(v.x, 0.01f * v.x); v.y = fmaxf(v.y, 0.01f * v.y); }
            orow[2 * p] = v.x; orow[2 * p + 1] = v.y;
        }
    } else if constexpr (TPG == 2) {
        unsigned long long acc = pack2(0.0f, 0.0f);
        #pragma unroll 4
        for (int k = 0; k < DIN; k++) {
            const float w = wt[k * DOUT + o];
            unsigned long long u = *(const unsigned long long*)(zin + k * TOKP + g * 2);
            acc = fma2(pack2(w, w), u, acc);
        }
        const float bv = bias[o];
        float2 v = unpack2(acc);
        v.x += bv; v.y += bv;
        if (LEAKY) { v.x = fmaxf(v.x, 0.01f * v.x); v.y = fmaxf(v.y, 0.01f * v.y); }
        float* orow = zout + o * TOKP + g * 2;
        orow[0] = v.x; orow[1] = v.y;
    } else {
        float acc = 0.0f;
        #pragma unroll 4
        for (int k = 0; k < DIN; k++)
            acc = fmaf(wt[k * DOUT + o], zin[k * TOKP + g], acc);
        float v = acc + bias[o];
        if (LEAKY) v = fmaxf(v, 0.01f * v);
        zout[o * TOKP + g] = v;
    }
}

// ---------------- RNN side of fused kernel -------------------------------------
__device__ __forceinline__ void rnn_cta(
    const float* __restrict__ x, const float* __restrict__ W_ih,
    const float* __restrict__ W_hh, const float* __restrict__ b_ih,
    const float* __restrict__ b_hh, float* __restrict__ out,
    float* sm, int b)
{
    float* ws = sm;                          // 256*WST
    float* xs = sm + 256 * WST;              // XCH*XD
    float* hb = sm + 256 * WST + XCH * XD;   // 2*HBS
    const int tid = threadIdx.x;
    const int jj = tid >> 1;
    const int half = tid & 1;
    const int o0 = jj, o1 = jj + 128;
    const int own = jj + half * 128;

    // register weights: rows o0,o1, k_rel [0,RP)
    unsigned long long w0[RP / 2], w1[RP / 2];
    {
        const ulonglong2* r0 = (const ulonglong2*)(W_hh + o0 * HH + half * 128);
        const ulonglong2* r1 = (const ulonglong2*)(W_hh + o1 * HH + half * 128);
        #pragma unroll
        for (int q = 0; q < RP / 4; q++) {
            ulonglong2 u = r0[q]; w0[2 * q] = u.x; w0[2 * q + 1] = u.y;
            ulonglong2 v = r1[q]; w1[2 * q] = v.x; w1[2 * q + 1] = v.y;
        }
    }
    // smem weights: k_rel [RP,128) -> 44 floats per row
    float* wsm = ws + tid * WST;
    {
        const float4* g0 = (const float4*)(W_hh + o0 * HH + half * 128 + RP);
        const float4* g1 = (const float4*)(W_hh + o1 * HH + half * 128 + RP);
        float4* s0 = (float4*)wsm;
        float4* s1 = (float4*)(wsm + 44);
        #pragma unroll
        for (int q = 0; q < 11; q++) { s0[q] = g0[q]; s1[q] = g1[q]; }
    }

    float wih[II];
    #pragma unroll
    for (int i = 0; i < II; i++) wih[i] = W_ih[own * II + i];
    const float bias = b_ih[own] + b_hh[own];

    for (int idx = tid; idx < 2 * HBS; idx += 256) hb[idx] = 0.0f;
    __syncthreads();

    const float4* xg = (const float4*)(x + (size_t)b * TT * XD);
    float* hout = g_ht + (size_t)b * TT * HH;

    int buf = 0;
    float hl = 0.0f;
    for (int t = 0; t < TT; t++) {
        const int tl = t & (XCH - 1);
        if (tl == 0) {
            const int base = t * 3;
            float4* xs4 = (float4*)xs;
            for (int idx = tid; idx < XCH * 3; idx += 256)
                xs4[idx] = xg[base + idx];
            __syncthreads();
        }
        const float4* xr = (const float4*)(xs + tl * XD);
        const float4 xa = xr[0];
        const float4 xb = xr[1];
        float xw = bias;
        xw = fmaf(xa.x, wih[0], xw);
        xw = fmaf(xa.y, wih[1], xw);
        xw = fmaf(xa.z, wih[2], xw);
        xw = fmaf(xa.w, wih[3], xw);
        xw = fmaf(xb.x, wih[4], xw);
        xw = fmaf(xb.y, wih[5], xw);
        xw = fmaf(xb.z, wih[6], xw);

        const ulonglong2* h2 = (const ulonglong2*)(hb + buf * HBS + half * 132);
        unsigned long long a0 = pack2(0.f, 0.f), a1 = a0, a2 = a0, a3 = a0;
        #pragma unroll
        for (int q = 0; q < 21; q++) {            // k_rel 0..83 (regs)
            ulonglong2 u = h2[q];
            a0 = fma2(w0[2 * q],     u.x, a0);
            a1 = fma2(w0[2 * q + 1], u.y, a1);
            a2 = fma2(w1[2 * q],     u.x, a2);
            a3 = fma2(w1[2 * q + 1], u.y, a3);
        }
        const ulonglong2* ws0 = (const ulonglong2*)wsm;
        const ulonglong2* ws1 = (const ulonglong2*)(wsm + 44);
        #pragma unroll
        for (int q = 0; q < 11; q++) {            // k_rel 84..127 (smem)
            ulonglong2 u = h2[21 + q];
            ulonglong2 wa = ws0[q];
            ulonglong2 wc = ws1[q];
            a0 = fma2(wa.x, u.x, a0);
            a1 = fma2(wa.y, u.y, a1);
            a2 = fma2(wc.x, u.x, a2);
            a3 = fma2(wc.y, u.y, a3);
        }
        float2 A = unpack2(a0), B2 = unpack2(a1), C = unpack2(a2), D = unpack2(a3);
        float p0 = (A.x + A.y) + (B2.x + B2.y);
        float p1 = (C.x + C.y) + (D.x + D.y);
        p0 += __shfl_xor_sync(0xFFFFFFFFu, p0, 1);
        p1 += __shfl_xor_sync(0xFFFFFFFFu, p1, 1);
        const float v = half ? p1 : p0;
        const float hn = tanhf(v + xw);

        hb[(buf ^ 1) * HBS + half * 132 + jj] = hn;
        hout[(size_t)t * HH + own] = hn;
        hl = hn;
        __syncthreads();
        if ((t & 31) == 31 && tid == 0) st_release(&g_prog[b], t + 1);
        buf ^= 1;
    }
    out[(size_t)BB * TT * II + (size_t)b * HH + own] = hl;
}

// ---------------- MLP worker side of fused kernel ------------------------------
__device__ __forceinline__ void mlp_worker(
    const float* __restrict__ x,
    const float* __restrict__ b0, const float* __restrict__ b1,
    const float* __restrict__ b2, const float* __restrict__ b3,
    const float* __restrict__ b4, const float* __restrict__ b5,
    const float* __restrict__ b6, float* __restrict__ out,
    float* sm, int wid)
{
    float* bufA = sm;
    float* bufB = sm + 264 * TOKP;
    const int tid = threadIdx.x;

    for (int blk = wid; blk < 128 * BB; blk += NWORK) {
        const int tc = blk >> 6;       // t-chunk (32 steps each)
        const int b = blk & 63;        // chain
        const int need = (tc + 1) * 32;

        if (tid == 0) {
            while (ld_acquire(&g_prog[b]) < need) __nanosleep(128);
        }
        __syncthreads();   // also protects bufA reuse across iterations

        const size_t tok0 = (size_t)b * TT + (size_t)tc * 32;

        // load ht (transposed) rows 0..255
        for (int idx = tid; idx < 32 * 256; idx += 256) {
            const int tk = idx >> 8, jj = idx & 255;
            bufA[jj * TOKP + tk] = g_ht[(tok0 + tk) * HH + jj];
        }
        // x_fixed rows 256..260
        for (int idx = tid; idx < 32 * 5; idx += 256) {
            const int tk = idx / 5, i = idx - tk * 5;
            bufA[(256 + i) * TOKP + tk] = x[(tok0 + tk) * XD + II + i];
        }
        __syncthreads();

        mlp_layer<256, 261, 32, true>(bufA, bufB, g_wt + OFF0, b0); __syncthreads();
        mlp_layer<128, 256, 16, true>(bufB, bufA, g_wt + OFF1, b1); __syncthreads();
        mlp_layer< 64, 128,  8, true>(bufA, bufB, g_wt + OFF2, b2); __syncthreads();
        mlp_layer< 32,  64,  4, true>(bufB, bufA, g_wt + OFF3, b3); __syncthreads();
        mlp_layer< 16,  32,  2, true>(bufA, bufB, g_wt + OFF4, b4); __syncthreads();
        mlp_layer<  8,  16,  1, true>(bufB, bufA, g_wt + OFF5, b5); __syncthreads();

        {
            const int o = tid & 7, g = tid >> 3;
            if (o < 7) {
                float acc = b6[o];
                #pragma unroll
                for (int k = 0; k < 8; k++)
                    acc = fmaf(g_wt[OFF6 + k * 7 + o], bufA[k * TOKP + g], acc);
                out[(tok0 + g) * II + o] = acc;
            }
        }
    }
}

// ---------------- fused kernel -------------------------------------------------
__global__ __launch_bounds__(256, 1) void fused_kernel(
    const float* __restrict__ x, const float* __restrict__ W_ih,
    const float* __restrict__ W_hh, const float* __restrict__ b_ih,
    const float* __restrict__ b_hh,
    const float* __restrict__ b0, const float* __restrict__ b1,
    const float* __restrict__ b2, const float* __restrict__ b3,
    const float* __restrict__ b4, const float* __restrict__ b5,
    const float* __restrict__ b6, float* __restrict__ out)
{
    extern __shared__ float sm[];
    if (blockIdx.x < NRNN) {
        rnn_cta(x, W_ih, W_hh, b_ih, b_hh, out, sm, blockIdx.x);
    } else {
        mlp_worker(x, b0, b1, b2, b3, b4, b5, b6, out, sm, blockIdx.x - NRNN);
    }
}

// ---------------- prep: transpose MLP weights + reset progress flags -----------
__global__ void prep_kernel(const float* __restrict__ W0, const float* __restrict__ W1,
                            const float* __restrict__ W2, const float* __restrict__ W3,
                            const float* __restrict__ W4, const float* __restrict__ W5,
                            const float* __restrict__ W6)
{
    if (blockIdx.x == 0 && threadIdx.x < BB) g_prog[threadIdx.x] = 0;

    const float* Ws[7] = {W0, W1, W2, W3, W4, W5, W6};
    const int douts[7] = {256, 128, 64, 32, 16, 8, 7};
    const int dins[7]  = {261, 256, 128, 64, 32, 16, 8};
    int off = 0;
    const int stride = gridDim.x * blockDim.x;
    const int tid0 = blockIdx.x * blockDim.x + threadIdx.x;
    for (int l = 0; l < 7; l++) {
        const int dout = douts[l], din = dins[l], n = dout * din;
        const float* W = Ws[l];
        for (int idx = tid0; idx < n; idx += stride) {
            const int k = idx / dout, o = idx - k * dout;
            g_wt[off + idx] = W[o * din + k];
        }
        off += n;
    }
}

// ---------------- launch -------------------------------------------------------
extern "C" void kernel_launch(void* const* d_in, const int* in_sizes, int n_in,
                              void* d_out, int out_size)
{
    const float* x    = (const float*)d_in[0];
    const float* W_ih = (const float*)d_in[1];
    const float* W_hh = (const float*)d_in[2];
    const float* b_ih = (const float*)d_in[3];
    const float* b_hh = (const float*)d_in[4];
    const float* W[7];
    const float* bb[7];
    for (int i = 0; i < 7; i++) {
        W[i]  = (const float*)d_in[5 + 2 * i];
        bb[i] = (const float*)d_in[6 + 2 * i];
    }
    float* out = (float*)d_out;

    static int attr_set = 0;
    if (!attr_set) {
        cudaFuncSetAttribute(fused_kernel,
                             cudaFuncAttributeMaxDynamicSharedMemorySize, FUSED_SMEM_B);
        attr_set = 1;
    }

    prep_kernel<<<64, 256>>>(W[0], W[1], W[2], W[3], W[4], W[5], W[6]);
    fused_kernel<<<NCTA, 256, FUSED_SMEM_B>>>(x, W_ih, W_hh, b_ih, b_hh,
                                              bb[0], bb[1], bb[2], bb[3],
                                              bb[4], bb[5], bb[6], out);
}

// round 3
// speedup vs baseline: 1.3148x; 1.1799x over previous
#include <cuda_runtime.h>
#include <cstdint>
#include <math.h>

// Problem dims
#define BB 64
#define TT 4096
#define HH 256
#define II 7
#define XD 12   // I + F

#define NRNN 64
#define NWORK 84
#define NCTA (NRNN + NWORK)
#define NTHR 512

// ---------------- device scratch ----------------------------------------------
__device__ float g_ht[(size_t)BB * TT * HH];   // RNN hidden states
__device__ float g_wt[110520];                 // transposed MLP weights
__device__ int   g_prog[BB];                   // RNN progress (steps done) per chain

// MLP layer offsets in g_wt
#define OFF0 0
#define OFF1 66816
#define OFF2 99584
#define OFF3 107776
#define OFF4 109824
#define OFF5 110336
#define OFF6 110464

// ---------------- f32x2 helpers ----------------------------------------------
__device__ __forceinline__ unsigned long long fma2(unsigned long long a,
                                                   unsigned long long b,
                                                   unsigned long long c) {
    unsigned long long d;
    asm("fma.rn.f32x2 %0, %1, %2, %3;" : "=l"(d) : "l"(a), "l"(b), "l"(c));
    return d;
}
__device__ __forceinline__ unsigned long long pack2(float lo, float hi) {
    unsigned long long d;
    asm("mov.b64 %0, {%1, %2};" : "=l"(d) : "f"(lo), "f"(hi));
    return d;
}
__device__ __forceinline__ float2 unpack2(unsigned long long v) {
    float lo, hi;
    asm("mov.b64 {%0, %1}, %2;" : "=f"(lo), "=f"(hi) : "l"(v));
    return make_float2(lo, hi);
}
__device__ __forceinline__ int ld_acquire(const int* p) {
    int v;
    asm volatile("ld.global.acquire.gpu.b32 %0, [%1];" : "=r"(v) : "l"(p));
    return v;
}
__device__ __forceinline__ void st_release(int* p, int v) {
    asm volatile("st.global.release.gpu.b32 [%0], %1;" :: "l"(p), "r"(v));
}
// tanh(x) = 1 - 2/(exp(2x)+1); exp inf/0 limits give +-1 correctly.
__device__ __forceinline__ float fast_tanh(float x) {
    float e = __expf(2.0f * x);
    return 1.0f - __fdividef(2.0f, e + 1.0f);
}

// ---------------- RNN config ---------------------------------------------------
// 512 threads. warp = tid>>5, lane = tid&31.
// half = lane>>4 (k-half), jj = warp*16 + (lane&15) (owned output row).
// Per thread: 128 weight floats for row jj, k in [half*128, half*128+128):
//   RP=84 in registers (42 ull), 44 in smem (stride WST=52 -> conflict-free).
#define RP   84
#define WST  52
#define XCH  256     // x staging chunk (steps)
#define HBS  264     // h layout: [0,128) | pad 4 | [132,260)

#define RNN_SMF (NTHR * WST + XCH * XD + 2 * HBS)   // 30224 floats

// ---------------- MLP config ---------------------------------------------------
#define TOKN 64
#define TOKP 68
#define MLP_SMF ((264 + 256) * TOKP)                // 35360 floats
#define FUSED_SMEM_B (MLP_SMF * 4)                  // 141440 B (max of both)

template<int DOUT, int DIN, int TPG, bool LEAKY>
__device__ __forceinline__ void mlp_layer(const float* __restrict__ zin,
                                          float* __restrict__ zout,
                                          const float* __restrict__ wt,
                                          const float* __restrict__ bias)
{
    const int tid = threadIdx.x;
    const int o = tid % DOUT;
    const int g = tid / DOUT;

    if constexpr (TPG >= 4) {
        constexpr int NP = TPG / 2;
        unsigned long long acc[NP];
        #pragma unroll
        for (int p = 0; p < NP; p++) acc[p] = pack2(0.0f, 0.0f);
        #pragma unroll 4
        for (int k = 0; k < DIN; k++) {
            const float w = wt[k * DOUT + o];
            const unsigned long long w2 = pack2(w, w);
            const ulonglong2* zr = (const ulonglong2*)(zin + k * TOKP + g * TPG);
            #pragma unroll
            for (int p = 0; p < TPG / 4; p++) {
                ulonglong2 u = zr[p];
                acc[2 * p]     = fma2(w2, u.x, acc[2 * p]);
                acc[2 * p + 1] = fma2(w2, u.y, acc[2 * p + 1]);
            }
        }
        const float bv = bias[o];
        float* orow = zout + o * TOKP + g * TPG;
        #pragma unroll
        for (int p = 0; p < NP; p++) {
            float2 v = unpack2(acc[p]);
            v.x += bv; v.y += bv;
            if (LEAKY) { v.x = fmaxf(v.x, 0.01f * v.x); v.y = fmaxf(v.y, 0.01f * v.y); }
            orow[2 * p] = v.x; orow[2 * p + 1] = v.y;
        }
    } else if constexpr (TPG == 2) {
        unsigned long long acc = pack2(0.0f, 0.0f);
        #pragma unroll 4
        for (int k = 0; k < DIN; k++) {
            const float w = wt[k * DOUT + o];
            unsigned long long u = *(const unsigned long long*)(zin + k * TOKP + g * 2);
            acc = fma2(pack2(w, w), u, acc);
        }
        const float bv = bias[o];
        float2 v = unpack2(acc);
        v.x += bv; v.y += bv;
        if (LEAKY) { v.x = fmaxf(v.x, 0.01f * v.x); v.y = fmaxf(v.y, 0.01f * v.y); }
        float* orow = zout + o * TOKP + g * 2;
        orow[0] = v.x; orow[1] = v.y;
    } else {
        float acc = 0.0f;
        #pragma unroll 4
        for (int k = 0; k < DIN; k++)
            acc = fmaf(wt[k * DOUT + o], zin[k * TOKP + g], acc);
        float v = acc + bias[o];
        if (LEAKY) v = fmaxf(v, 0.01f * v);
        zout[o * TOKP + g] = v;
    }
}

// ---------------- RNN side -----------------------------------------------------
__device__ __forceinline__ void rnn_cta(
    const float* __restrict__ x, const float* __restrict__ W_ih,
    const float* __restrict__ W_hh, const float* __restrict__ b_ih,
    const float* __restrict__ b_hh, float* __restrict__ out,
    float* sm, int b)
{
    float* ws = sm;                            // NTHR*WST
    float* xs = sm + NTHR * WST;               // XCH*XD
    float* hb = sm + NTHR * WST + XCH * XD;    // 2*HBS
    const int tid = threadIdx.x;
    const int warp = tid >> 5, lane = tid & 31;
    const int half = lane >> 4;
    const int jj = (warp << 4) + (lane & 15);
    const int hoff = jj + ((jj >> 7) << 2);    // position of h[jj] in padded layout

    const float* wrow = W_hh + jj * HH + half * 128;

    // register weights: k_rel [0,RP)
    unsigned long long w2[RP / 2];
    {
        const ulonglong2* wr = (const ulonglong2*)wrow;
        #pragma unroll
        for (int q = 0; q < RP / 4; q++) {
            ulonglong2 u = wr[q];
            w2[2 * q] = u.x; w2[2 * q + 1] = u.y;
        }
    }
    // smem weights: k_rel [RP,128) -> 44 floats
    float* wsm = ws + tid * WST;
    {
        const float4* gt = (const float4*)(wrow + RP);
        float4* st = (float4*)wsm;
        #pragma unroll
        for (int q = 0; q < 11; q++) st[q] = gt[q];
    }

    float wih[II];
    #pragma unroll
    for (int i = 0; i < II; i++) wih[i] = W_ih[jj * II + i];
    const float bias = b_ih[jj] + b_hh[jj];

    for (int idx = tid; idx < 2 * HBS; idx += NTHR) hb[idx] = 0.0f;
    __syncthreads();

    const float4* xg = (const float4*)(x + (size_t)b * TT * XD);
    float* hout = g_ht + (size_t)b * TT * HH;

    int buf = 0;
    float hl = 0.0f;
    for (int t = 0; t < TT; t++) {
        const int tl = t & (XCH - 1);
        if (tl == 0) {
            const int base = t * 3;
            float4* xs4 = (float4*)xs;
            for (int idx = tid; idx < XCH * 3; idx += NTHR)
                xs4[idx] = xg[base + idx];
            __syncthreads();
        }
        const float4* xr = (const float4*)(xs + tl * XD);
        const float4 xa = xr[0];
        const float4 xb = xr[1];
        float xw = bias;
        xw = fmaf(xa.x, wih[0], xw);
        xw = fmaf(xa.y, wih[1], xw);
        xw = fmaf(xa.z, wih[2], xw);
        xw = fmaf(xa.w, wih[3], xw);
        xw = fmaf(xb.x, wih[4], xw);
        xw = fmaf(xb.y, wih[5], xw);
        xw = fmaf(xb.z, wih[6], xw);

        const ulonglong2* h2 = (const ulonglong2*)(hb + buf * HBS + half * 132);
        unsigned long long a0 = pack2(0.f, 0.f), a1 = a0;
        #pragma unroll
        for (int q = 0; q < RP / 4; q++) {           // k_rel 0..83 (regs)
            ulonglong2 u = h2[q];
            a0 = fma2(w2[2 * q],     u.x, a0);
            a1 = fma2(w2[2 * q + 1], u.y, a1);
        }
        const ulonglong2* wsr = (const ulonglong2*)wsm;
        #pragma unroll
        for (int q = 0; q < 11; q++) {               // k_rel 84..127 (smem)
            ulonglong2 u = h2[RP / 4 + q];
            ulonglong2 wv = wsr[q];
            a0 = fma2(wv.x, u.x, a0);
            a1 = fma2(wv.y, u.y, a1);
        }
        float2 A = unpack2(a0), B2 = unpack2(a1);
        float p = (A.x + A.y) + (B2.x + B2.y);
        p += __shfl_xor_sync(0xFFFFFFFFu, p, 16);

        if (half == 0) {
            const float hn = fast_tanh(p + xw);
            hb[(buf ^ 1) * HBS + hoff] = hn;
            hout[(size_t)t * HH + jj] = hn;
            hl = hn;
        }
        __syncthreads();
        if ((t & 63) == 63 && tid == 0) st_release(&g_prog[b], t + 1);
        buf ^= 1;
    }
    if (half == 0)
        out[(size_t)BB * TT * II + (size_t)b * HH + jj] = hl;
}

// ---------------- MLP worker side ----------------------------------------------
__device__ __forceinline__ void mlp_worker(
    const float* __restrict__ x,
    const float* __restrict__ b0, const float* __restrict__ b1,
    const float* __restrict__ b2, const float* __restrict__ b3,
    const float* __restrict__ b4, const float* __restrict__ b5,
    const float* __restrict__ b6, float* __restrict__ out,
    float* sm, int wid)
{
    float* bufA = sm;
    float* bufB = sm + 264 * TOKP;
    const int tid = threadIdx.x;

    // 64 chains x 64 chunks of 64 steps
    for (int blk = wid; blk < 64 * BB; blk += NWORK) {
        const int tc = blk >> 6;
        const int b = blk & 63;
        const int need = (tc + 1) * 64;

        if (tid == 0) {
            while (ld_acquire(&g_prog[b]) < need) __nanosleep(128);
        }
        __syncthreads();   // also protects buf reuse across iterations

        const size_t tok0 = (size_t)b * TT + (size_t)tc * TOKN;

        // ht (transposed) rows 0..255
        for (int idx = tid; idx < TOKN * 256; idx += NTHR) {
            const int tk = idx >> 8, jj = idx & 255;
            bufA[jj * TOKP + tk] = g_ht[(tok0 + tk) * HH + jj];
        }
        // x_fixed rows 256..260
        for (int idx = tid; idx < TOKN * 5; idx += NTHR) {
            const int tk = idx / 5, i = idx - tk * 5;
            bufA[(256 + i) * TOKP + tk] = x[(tok0 + tk) * XD + II + i];
        }
        __syncthreads();

        mlp_layer<256, 261, 32, true>(bufA, bufB, g_wt + OFF0, b0); __syncthreads();
        mlp_layer<128, 256, 16, true>(bufB, bufA, g_wt + OFF1, b1); __syncthreads();
        mlp_layer< 64, 128,  8, true>(bufA, bufB, g_wt + OFF2, b2); __syncthreads();
        mlp_layer< 32,  64,  4, true>(bufB, bufA, g_wt + OFF3, b3); __syncthreads();
        mlp_layer< 16,  32,  2, true>(bufA, bufB, g_wt + OFF4, b4); __syncthreads();
        mlp_layer<  8,  16,  1, true>(bufB, bufA, g_wt + OFF5, b5); __syncthreads();

        {
            const int o = tid & 7, g = tid >> 3;   // g in [0,64)
            if (o < 7) {
                float acc = b6[o];
                #pragma unroll
                for (int k = 0; k < 8; k++)
                    acc = fmaf(g_wt[OFF6 + k * 7 + o], bufA[k * TOKP + g], acc);
                out[(tok0 + g) * II + o] = acc;
            }
        }
    }
}

// ---------------- fused kernel -------------------------------------------------
__global__ __launch_bounds__(NTHR, 1) void fused_kernel(
    const float* __restrict__ x, const float* __restrict__ W_ih,
    const float* __restrict__ W_hh, const float* __restrict__ b_ih,
    const float* __restrict__ b_hh,
    const float* __restrict__ b0, const float* __restrict__ b1,
    const float* __restrict__ b2, const float* __restrict__ b3,
    const float* __restrict__ b4, const float* __restrict__ b5,
    const float* __restrict__ b6, float* __restrict__ out)
{
    extern __shared__ float sm[];
    if (blockIdx.x < NRNN) {
        rnn_cta(x, W_ih, W_hh, b_ih, b_hh, out, sm, blockIdx.x);
    } else {
        mlp_worker(x, b0, b1, b2, b3, b4, b5, b6, out, sm, blockIdx.x - NRNN);
    }
}

// ---------------- prep: transpose MLP weights + reset progress flags -----------
__global__ void prep_kernel(const float* __restrict__ W0, const float* __restrict__ W1,
                            const float* __restrict__ W2, const float* __restrict__ W3,
                            const float* __restrict__ W4, const float* __restrict__ W5,
                            const float* __restrict__ W6)
{
    if (blockIdx.x == 0 && threadIdx.x < BB) g_prog[threadIdx.x] = 0;

    const float* Ws[7] = {W0, W1, W2, W3, W4, W5, W6};
    const int douts[7] = {256, 128, 64, 32, 16, 8, 7};
    const int dins[7]  = {261, 256, 128, 64, 32, 16, 8};
    int off = 0;
    const int stride = gridDim.x * blockDim.x;
    const int tid0 = blockIdx.x * blockDim.x + threadIdx.x;
    for (int l = 0; l < 7; l++) {
        const int dout = douts[l], din = dins[l], n = dout * din;
        const float* W = Ws[l];
        for (int idx = tid0; idx < n; idx += stride) {
            const int k = idx / dout, o = idx - k * dout;
            g_wt[off + idx] = W[o * din + k];
        }
        off += n;
    }
}

// ---------------- launch -------------------------------------------------------
extern "C" void kernel_launch(void* const* d_in, const int* in_sizes, int n_in,
                              void* d_out, int out_size)
{
    const float* x    = (const float*)d_in[0];
    const float* W_ih = (const float*)d_in[1];
    const float* W_hh = (const float*)d_in[2];
    const float* b_ih = (const float*)d_in[3];
    const float* b_hh = (const float*)d_in[4];
    const float* W[7];
    const float* bb[7];
    for (int i = 0; i < 7; i++) {
        W[i]  = (const float*)d_in[5 + 2 * i];
        bb[i] = (const float*)d_in[6 + 2 * i];
    }
    float* out = (float*)d_out;

    static int attr_set = 0;
    if (!attr_set) {
        cudaFuncSetAttribute(fused_kernel,
                             cudaFuncAttributeMaxDynamicSharedMemorySize, FUSED_SMEM_B);
        attr_set = 1;
    }

    prep_kernel<<<64, 256>>>(W[0], W[1], W[2], W[3], W[4], W[5], W[6]);
    fused_kernel<<<NCTA, NTHR, FUSED_SMEM_B>>>(x, W_ih, W_hh, b_ih, b_hh,
                                               bb[0], bb[1], bb[2], bb[3],
                                               bb[4], bb[5], bb[6], out);
}

// round 4
// speedup vs baseline: 1.4520x; 1.1043x over previous
#include <cuda_runtime.h>
#include <cstdint>
#include <math.h>

// Problem dims
#define BB 64
#define TT 4096
#define HH 256
#define II 7
#define XD 12   // I + F

#define NRNN 64
#define NWORK 84
#define NCTA (NRNN + NWORK)
#define NTHR 512

// ---------------- device scratch ----------------------------------------------
__device__ float g_ht[(size_t)BB * TT * HH];   // RNN hidden states
__device__ float g_wt[110520];                 // transposed MLP weights
__device__ int   g_prog[BB];                   // RNN progress (steps done) per chain

// MLP layer offsets in g_wt
#define OFF0 0
#define OFF1 66816
#define OFF2 99584
#define OFF3 107776
#define OFF4 109824
#define OFF5 110336
#define OFF6 110464

// ---------------- f32x2 helpers ----------------------------------------------
__device__ __forceinline__ unsigned long long fma2(unsigned long long a,
                                                   unsigned long long b,
                                                   unsigned long long c) {
    unsigned long long d;
    asm("fma.rn.f32x2 %0, %1, %2, %3;" : "=l"(d) : "l"(a), "l"(b), "l"(c));
    return d;
}
__device__ __forceinline__ unsigned long long pack2(float lo, float hi) {
    unsigned long long d;
    asm("mov.b64 %0, {%1, %2};" : "=l"(d) : "f"(lo), "f"(hi));
    return d;
}
__device__ __forceinline__ float2 unpack2(unsigned long long v) {
    float lo, hi;
    asm("mov.b64 {%0, %1}, %2;" : "=f"(lo), "=f"(hi) : "l"(v));
    return make_float2(lo, hi);
}
__device__ __forceinline__ int ld_acquire(const int* p) {
    int v;
    asm volatile("ld.global.acquire.gpu.b32 %0, [%1];" : "=r"(v) : "l"(p));
    return v;
}
__device__ __forceinline__ void st_release(int* p, int v) {
    asm volatile("st.global.release.gpu.b32 [%0], %1;" :: "l"(p), "r"(v));
}
// tanh(x) = 1 - 2/(exp(2x)+1); exp inf/0 limits give +-1 correctly.
__device__ __forceinline__ float fast_tanh(float x) {
    float e = __expf(2.0f * x);
    return 1.0f - __fdividef(2.0f, e + 1.0f);
}

// ---------------- RNN config ---------------------------------------------------
// 512 threads. warp = tid>>5, lane = tid&31.
// q = lane>>3 (k-quarter, 64 k-values), r8 = lane&7.
// Thread handles rows {jj, jj+128} with jj = warp*8 + r8, k in [q*64, q*64+64).
// Per row: 36 weight floats in regs, 28 in smem.
#define RPW 36
#define SPW 28
#define WST2 60      // per-thread smem weight stride (floats; 56 used)
#define XCH  256     // x staging chunk (steps)
#define HQ   68      // h quarter stride (64 used + 4 pad) -> conflict-free LDS
#define HBS2 288     // h buffer stride (4*HQ = 272, padded)

// ---------------- MLP config ---------------------------------------------------
#define TOKN 64
#define TOKP 68
#define MLP_SMF ((264 + 256) * TOKP)                // 35360 floats
#define FUSED_SMEM_B (MLP_SMF * 4)                  // 141440 B (max of both sides)

template<int DOUT, int DIN, int TPG, bool LEAKY>
__device__ __forceinline__ void mlp_layer(const float* __restrict__ zin,
                                          float* __restrict__ zout,
                                          const float* __restrict__ wt,
                                          const float* __restrict__ bias)
{
    const int tid = threadIdx.x;
    const int o = tid % DOUT;
    const int g = tid / DOUT;

    if constexpr (TPG >= 4) {
        constexpr int NP = TPG / 2;
        unsigned long long acc[NP];
        #pragma unroll
        for (int p = 0; p < NP; p++) acc[p] = pack2(0.0f, 0.0f);
        #pragma unroll 4
        for (int k = 0; k < DIN; k++) {
            const float w = wt[k * DOUT + o];
            const unsigned long long w2 = pack2(w, w);
            const ulonglong2* zr = (const ulonglong2*)(zin + k * TOKP + g * TPG);
            #pragma unroll
            for (int p = 0; p < TPG / 4; p++) {
                ulonglong2 u = zr[p];
                acc[2 * p]     = fma2(w2, u.x, acc[2 * p]);
                acc[2 * p + 1] = fma2(w2, u.y, acc[2 * p + 1]);
            }
        }
        const float bv = bias[o];
        float* orow = zout + o * TOKP + g * TPG;
        #pragma unroll
        for (int p = 0; p < NP; p++) {
            float2 v = unpack2(acc[p]);
            v.x += bv; v.y += bv;
            if (LEAKY) { v.x = fmaxf(v.x, 0.01f * v.x); v.y = fmaxf(v.y, 0.01f * v.y); }
            orow[2 * p] = v.x; orow[2 * p + 1] = v.y;
        }
    } else if constexpr (TPG == 2) {
        unsigned long long acc = pack2(0.0f, 0.0f);
        #pragma unroll 4
        for (int k = 0; k < DIN; k++) {
            const float w = wt[k * DOUT + o];
            unsigned long long u = *(const unsigned long long*)(zin + k * TOKP + g * 2);
            acc = fma2(pack2(w, w), u, acc);
        }
        const float bv = bias[o];
        float2 v = unpack2(acc);
        v.x += bv; v.y += bv;
        if (LEAKY) { v.x = fmaxf(v.x, 0.01f * v.x); v.y = fmaxf(v.y, 0.01f * v.y); }
        float* orow = zout + o * TOKP + g * 2;
        orow[0] = v.x; orow[1] = v.y;
    } else {
        float acc = 0.0f;
        #pragma unroll 4
        for (int k = 0; k < DIN; k++)
            acc = fmaf(wt[k * DOUT + o], zin[k * TOKP + g], acc);
        float v = acc + bias[o];
        if (LEAKY) v = fmaxf(v, 0.01f * v);
        zout[o * TOKP + g] = v;
    }
}

// ---------------- RNN side -----------------------------------------------------
__device__ __forceinline__ void rnn_cta(
    const float* __restrict__ x, const float* __restrict__ W_ih,
    const float* __restrict__ W_hh, const float* __restrict__ b_ih,
    const float* __restrict__ b_hh, float* __restrict__ out,
    float* sm, int b)
{
    float* ws = sm;                            // NTHR*WST2
    float* xs = sm + NTHR * WST2;              // XCH*XD
    float* hb = sm + NTHR * WST2 + XCH * XD;   // 2*HBS2
    const int tid = threadIdx.x;
    const int warp = tid >> 5, lane = tid & 31;
    const int q = lane >> 3;
    const int r8 = lane & 7;
    const int jj = (warp << 3) + r8;           // [0,128)
    const int row1 = jj + 128;

    // weight pointers for this thread's k-range
    const float* wr0 = W_hh + jj * HH + q * 64;
    const float* wr1 = W_hh + row1 * HH + q * 64;

    // register weights: k_rel [0,36) for both rows
    unsigned long long w0[RPW / 2], w1[RPW / 2];
    {
        const ulonglong2* p0 = (const ulonglong2*)wr0;
        const ulonglong2* p1 = (const ulonglong2*)wr1;
        #pragma unroll
        for (int i = 0; i < RPW / 4; i++) {
            ulonglong2 u = p0[i]; w0[2 * i] = u.x; w0[2 * i + 1] = u.y;
            ulonglong2 v = p1[i]; w1[2 * i] = v.x; w1[2 * i + 1] = v.y;
        }
    }
    // smem weights: k_rel [36,64) -> 28 floats per row
    float* wsm = ws + tid * WST2;
    {
        const float4* g0 = (const float4*)(wr0 + RPW);
        const float4* g1 = (const float4*)(wr1 + RPW);
        float4* s0 = (float4*)wsm;
        float4* s1 = (float4*)(wsm + SPW);
        #pragma unroll
        for (int i = 0; i < SPW / 4; i++) { s0[i] = g0[i]; s1[i] = g1[i]; }
    }

    // lanes q==0 finalize row jj, q==1 finalize row jj+128
    const int myrow = (q == 1) ? row1 : jj;
    float wih[II];
    float bias = 0.0f;
    if (q < 2) {
        #pragma unroll
        for (int i = 0; i < II; i++) wih[i] = W_ih[myrow * II + i];
        bias = b_ih[myrow] + b_hh[myrow];
    }
    const int hq = myrow >> 6;                 // quarter of owned row
    const int hoff = hq * HQ + (myrow & 63);

    for (int idx = tid; idx < 2 * HBS2; idx += NTHR) hb[idx] = 0.0f;
    __syncthreads();

    const float4* xg = (const float4*)(x + (size_t)b * TT * XD);
    float* hout = g_ht + (size_t)b * TT * HH;

    int buf = 0;
    float hl = 0.0f;
    for (int t = 0; t < TT; t++) {
        const int tl = t & (XCH - 1);
        if (tl == 0) {
            const int base = t * 3;
            float4* xs4 = (float4*)xs;
            for (int idx = tid; idx < XCH * 3; idx += NTHR)
                xs4[idx] = xg[base + idx];
            __syncthreads();
        }

        float xw = 0.0f;
        if (q < 2) {
            const float4* xr = (const float4*)(xs + tl * XD);
            const float4 xa = xr[0];
            const float4 xb = xr[1];
            xw = bias;
            xw = fmaf(xa.x, wih[0], xw);
            xw = fmaf(xa.y, wih[1], xw);
            xw = fmaf(xa.z, wih[2], xw);
            xw = fmaf(xa.w, wih[3], xw);
            xw = fmaf(xb.x, wih[4], xw);
            xw = fmaf(xb.y, wih[5], xw);
            xw = fmaf(xb.z, wih[6], xw);
        }

        // h for this thread's k-quarter: 64 floats = 16 ulonglong2
        const ulonglong2* h2 = (const ulonglong2*)(hb + buf * HBS2 + q * HQ);
        unsigned long long a0 = pack2(0.f, 0.f), a1 = a0, a2 = a0, a3 = a0;
        #pragma unroll
        for (int i = 0; i < RPW / 4; i++) {          // k_rel 0..35 (regs)
            ulonglong2 u = h2[i];
            a0 = fma2(w0[2 * i],     u.x, a0);
            a1 = fma2(w0[2 * i + 1], u.y, a1);
            a2 = fma2(w1[2 * i],     u.x, a2);
            a3 = fma2(w1[2 * i + 1], u.y, a3);
        }
        const ulonglong2* s0 = (const ulonglong2*)wsm;
        const ulonglong2* s1 = (const ulonglong2*)(wsm + SPW);
        #pragma unroll
        for (int i = 0; i < SPW / 4; i++) {          // k_rel 36..63 (smem)
            ulonglong2 u = h2[RPW / 4 + i];
            ulonglong2 wa = s0[i];
            ulonglong2 wb = s1[i];
            a0 = fma2(wa.x, u.x, a0);
            a1 = fma2(wa.y, u.y, a1);
            a2 = fma2(wb.x, u.x, a2);
            a3 = fma2(wb.y, u.y, a3);
        }
        float2 A = unpack2(a0), B2 = unpack2(a1);
        float2 C = unpack2(a2), D = unpack2(a3);
        float p0 = (A.x + A.y) + (B2.x + B2.y);      // partial, row jj
        float p1 = (C.x + C.y) + (D.x + D.y);        // partial, row jj+128
        p0 += __shfl_xor_sync(0xFFFFFFFFu, p0, 8);
        p0 += __shfl_xor_sync(0xFFFFFFFFu, p0, 16);
        p1 += __shfl_xor_sync(0xFFFFFFFFu, p1, 8);
        p1 += __shfl_xor_sync(0xFFFFFFFFu, p1, 16);

        if (q < 2) {
            const float s = (q == 1) ? p1 : p0;
            const float hn = fast_tanh(s + xw);
            hb[(buf ^ 1) * HBS2 + hoff] = hn;
            hout[(size_t)t * HH + myrow] = hn;
            hl = hn;
        }
        __syncthreads();
        if ((t & 63) == 63 && tid == 0) st_release(&g_prog[b], t + 1);
        buf ^= 1;
    }
    if (q < 2)
        out[(size_t)BB * TT * II + (size_t)b * HH + myrow] = hl;
}

// ---------------- MLP worker side ----------------------------------------------
__device__ __forceinline__ void mlp_worker(
    const float* __restrict__ x,
    const float* __restrict__ b0, const float* __restrict__ b1,
    const float* __restrict__ b2, const float* __restrict__ b3,
    const float* __restrict__ b4, const float* __restrict__ b5,
    const float* __restrict__ b6, float* __restrict__ out,
    float* sm, int wid)
{
    float* bufA = sm;
    float* bufB = sm + 264 * TOKP;
    const int tid = threadIdx.x;

    // 64 chains x 64 chunks of 64 steps
    for (int blk = wid; blk < 64 * BB; blk += NWORK) {
        const int tc = blk >> 6;
        const int b = blk & 63;
        const int need = (tc + 1) * 64;

        if (tid == 0) {
            while (ld_acquire(&g_prog[b]) < need) __nanosleep(128);
        }
        __syncthreads();   // also protects buf reuse across iterations

        const size_t tok0 = (size_t)b * TT + (size_t)tc * TOKN;

        // ht (transposed) rows 0..255
        for (int idx = tid; idx < TOKN * 256; idx += NTHR) {
            const int tk = idx >> 8, jj = idx & 255;
            bufA[jj * TOKP + tk] = g_ht[(tok0 + tk) * HH + jj];
        }
        // x_fixed rows 256..260
        for (int idx = tid; idx < TOKN * 5; idx += NTHR) {
            const int tk = idx / 5, i = idx - tk * 5;
            bufA[(256 + i) * TOKP + tk] = x[(tok0 + tk) * XD + II + i];
        }
        __syncthreads();

        mlp_layer<256, 261, 32, true>(bufA, bufB, g_wt + OFF0, b0); __syncthreads();
        mlp_layer<128, 256, 16, true>(bufB, bufA, g_wt + OFF1, b1); __syncthreads();
        mlp_layer< 64, 128,  8, true>(bufA, bufB, g_wt + OFF2, b2); __syncthreads();
        mlp_layer< 32,  64,  4, true>(bufB, bufA, g_wt + OFF3, b3); __syncthreads();
        mlp_layer< 16,  32,  2, true>(bufA, bufB, g_wt + OFF4, b4); __syncthreads();
        mlp_layer<  8,  16,  1, true>(bufB, bufA, g_wt + OFF5, b5); __syncthreads();

        {
            const int o = tid & 7, g = tid >> 3;   // g in [0,64)
            if (o < 7) {
                float acc = b6[o];
                #pragma unroll
                for (int k = 0; k < 8; k++)
                    acc = fmaf(g_wt[OFF6 + k * 7 + o], bufA[k * TOKP + g], acc);
                out[(tok0 + g) * II + o] = acc;
            }
        }
    }
}

// ---------------- fused kernel -------------------------------------------------
__global__ __launch_bounds__(NTHR, 1) void fused_kernel(
    const float* __restrict__ x, const float* __restrict__ W_ih,
    const float* __restrict__ W_hh, const float* __restrict__ b_ih,
    const float* __restrict__ b_hh,
    const float* __restrict__ b0, const float* __restrict__ b1,
    const float* __restrict__ b2, const float* __restrict__ b3,
    const float* __restrict__ b4, const float* __restrict__ b5,
    const float* __restrict__ b6, float* __restrict__ out)
{
    extern __shared__ float sm[];
    if (blockIdx.x < NRNN) {
        rnn_cta(x, W_ih, W_hh, b_ih, b_hh, out, sm, blockIdx.x);
    } else {
        mlp_worker(x, b0, b1, b2, b3, b4, b5, b6, out, sm, blockIdx.x - NRNN);
    }
}

// ---------------- prep: transpose MLP weights + reset progress flags -----------
__global__ void prep_kernel(const float* __restrict__ W0, const float* __restrict__ W1,
                            const float* __restrict__ W2, const float* __restrict__ W3,
                            const float* __restrict__ W4, const float* __restrict__ W5,
                            const float* __restrict__ W6)
{
    if (blockIdx.x == 0 && threadIdx.x < BB) g_prog[threadIdx.x] = 0;

    const float* Ws[7] = {W0, W1, W2, W3, W4, W5, W6};
    const int douts[7] = {256, 128, 64, 32, 16, 8, 7};
    const int dins[7]  = {261, 256, 128, 64, 32, 16, 8};
    int off = 0;
    const int stride = gridDim.x * blockDim.x;
    const int tid0 = blockIdx.x * blockDim.x + threadIdx.x;
    for (int l = 0; l < 7; l++) {
        const int dout = douts[l], din = dins[l], n = dout * din;
        const float* W = Ws[l];
        for (int idx = tid0; idx < n; idx += stride) {
            const int k = idx / dout, o = idx - k * dout;
            g_wt[off + idx] = W[o * din + k];
        }
        off += n;
    }
}

// ---------------- launch -------------------------------------------------------
extern "C" void kernel_launch(void* const* d_in, const int* in_sizes, int n_in,
                              void* d_out, int out_size)
{
    const float* x    = (const float*)d_in[0];
    const float* W_ih = (const float*)d_in[1];
    const float* W_hh = (const float*)d_in[2];
    const float* b_ih = (const float*)d_in[3];
    const float* b_hh = (const float*)d_in[4];
    const float* W[7];
    const float* bb[7];
    for (int i = 0; i < 7; i++) {
        W[i]  = (const float*)d_in[5 + 2 * i];
        bb[i] = (const float*)d_in[6 + 2 * i];
    }
    float* out = (float*)d_out;

    static int attr_set = 0;
    if (!attr_set) {
        cudaFuncSetAttribute(fused_kernel,
                             cudaFuncAttributeMaxDynamicSharedMemorySize, FUSED_SMEM_B);
        attr_set = 1;
    }

    prep_kernel<<<64, 256>>>(W[0], W[1], W[2], W[3], W[4], W[5], W[6]);
    fused_kernel<<<NCTA, NTHR, FUSED_SMEM_B>>>(x, W_ih, W_hh, b_ih, b_hh,
                                               bb[0], bb[1], bb[2], bb[3],
                                               bb[4], bb[5], bb[6], out);
}

// round 6
// speedup vs baseline: 1.5627x; 1.0762x over previous
#include <cuda_runtime.h>
#include <cstdint>
#include <math.h>

// Problem dims
#define BB 64
#define TT 4096
#define HH 256
#define II 7
#define XD 12   // I + F

#define NRNN 64
#define NWORK 84
#define NCTA (NRNN + NWORK)
#define NT2 256

// ---------------- device scratch ----------------------------------------------
__device__ float g_ht[(size_t)BB * TT * HH];   // RNN hidden states (256 MB)
__device__ float g_xw[(size_t)BB * TT * HH];   // precomputed xW + biases (256 MB)
__device__ float g_wt[110520];                 // transposed MLP weights
__device__ int   g_prog[BB];                   // RNN progress per chain
__device__ int   g_tick;                       // MLP chunk ticket counter

// MLP layer offsets in g_wt
#define OFF0 0
#define OFF1 66816
#define OFF2 99584
#define OFF3 107776
#define OFF4 109824
#define OFF5 110336
#define OFF6 110464

// ---------------- helpers ------------------------------------------------------
__device__ __forceinline__ unsigned long long fma2(unsigned long long a,
                                                   unsigned long long b,
                                                   unsigned long long c) {
    unsigned long long d;
    asm("fma.rn.f32x2 %0, %1, %2, %3;" : "=l"(d) : "l"(a), "l"(b), "l"(c));
    return d;
}
__device__ __forceinline__ unsigned long long pack2(float lo, float hi) {
    unsigned long long d;
    asm("mov.b64 %0, {%1, %2};" : "=l"(d) : "f"(lo), "f"(hi));
    return d;
}
__device__ __forceinline__ float2 unpack2(unsigned long long v) {
    float lo, hi;
    asm("mov.b64 {%0, %1}, %2;" : "=f"(lo), "=f"(hi) : "l"(v));
    return make_float2(lo, hi);
}
__device__ __forceinline__ float rsum4(unsigned long long A, unsigned long long B) {
    float2 a = unpack2(A), b = unpack2(B);
    return (a.x + a.y) + (b.x + b.y);
}
__device__ __forceinline__ int ld_acquire(const int* p) {
    int v;
    asm volatile("ld.global.acquire.gpu.b32 %0, [%1];" : "=r"(v) : "l"(p));
    return v;
}
__device__ __forceinline__ void st_release(int* p, int v) {
    asm volatile("st.global.release.gpu.b32 [%0], %1;" :: "l"(p), "r"(v));
}
__device__ __forceinline__ float fast_tanh(float x) {
    float e = __expf(2.0f * x);
    return 1.0f - __fdividef(2.0f, e + 1.0f);
}
__device__ __forceinline__ void cpa16(uint32_t s, const void* g) {
    asm volatile("cp.async.cg.shared.global [%0], [%1], 16;" :: "r"(s), "l"(g));
}
__device__ __forceinline__ void cpa_commit() {
    asm volatile("cp.async.commit_group;" ::: "memory");
}

// ---------------- RNN config ---------------------------------------------------
// 256 threads/CTA, one CTA per chain. warp w, lane: q = lane>>3, r = lane&7.
// Thread: rows j0..j0+3 (j0 = w*32 + r*4), k in [q*64, q*64+64).
// Per row: 52 weight floats in regs (104 ull total), 12 in smem.
#define RWP 52
#define SWP 12
#define WTST 52       // per-thread smem weight stride (48 used + 4 pad)
#define HQ 68         // h quarter stride
#define HBF 272       // h buffer stride (4*HQ)
#define CH 32         // xw chunk (steps)
#define NCH (TT / CH)

#define RNN_SMF (NT2 * WTST + 2 * CH * HH + 2 * HBF)   // 30240 floats = 120960 B

// ---------------- MLP config ---------------------------------------------------
#define TOKN 64
#define TOKP 68
#define MLP_SMF ((264 + 256) * TOKP)                   // 35360 floats = 141440 B
#define FUSED_SMEM_B (MLP_SMF * 4)

template<int DOUT, int DIN, int TPG, bool LEAKY>
__device__ __forceinline__ void mlp_layer(const float* __restrict__ zin,
                                          float* __restrict__ zout,
                                          const float* __restrict__ wt,
                                          const float* __restrict__ bias)
{
    const int tid = threadIdx.x;
    const int o = tid % DOUT;
    const int g = tid / DOUT;

    if constexpr (TPG >= 4) {
        constexpr int NP = TPG / 2;
        unsigned long long acc[NP];
        #pragma unroll
        for (int p = 0; p < NP; p++) acc[p] = pack2(0.0f, 0.0f);
        #pragma unroll 4
        for (int k = 0; k < DIN; k++) {
            const float w = wt[k * DOUT + o];
            const unsigned long long w2 = pack2(w, w);
            const ulonglong2* zr = (const ulonglong2*)(zin + k * TOKP + g * TPG);
            #pragma unroll
            for (int p = 0; p < TPG / 4; p++) {
                ulonglong2 u = zr[p];
                acc[2 * p]     = fma2(w2, u.x, acc[2 * p]);
                acc[2 * p + 1] = fma2(w2, u.y, acc[2 * p + 1]);
            }
        }
        const float bv = bias[o];
        float* orow = zout + o * TOKP + g * TPG;
        #pragma unroll
        for (int p = 0; p < NP; p++) {
            float2 v = unpack2(acc[p]);
            v.x += bv; v.y += bv;
            if (LEAKY) { v.x = fmaxf(v.x, 0.01f * v.x); v.y = fmaxf(v.y, 0.01f * v.y); }
            orow[2 * p] = v.x; orow[2 * p + 1] = v.y;
        }
    } else if constexpr (TPG == 2) {
        unsigned long long acc = pack2(0.0f, 0.0f);
        #pragma unroll 4
        for (int k = 0; k < DIN; k++) {
            const float w = wt[k * DOUT + o];
            unsigned long long u = *(const unsigned long long*)(zin + k * TOKP + g * 2);
            acc = fma2(pack2(w, w), u, acc);
        }
        const float bv = bias[o];
        float2 v = unpack2(acc);
        v.x += bv; v.y += bv;
        if (LEAKY) { v.x = fmaxf(v.x, 0.01f * v.x); v.y = fmaxf(v.y, 0.01f * v.y); }
        float* orow = zout + o * TOKP + g * 2;
        orow[0] = v.x; orow[1] = v.y;
    }
}

// ---------------- RNN side -----------------------------------------------------
__device__ void rnn_cta(const float* __restrict__ W_hh, float* __restrict__ out,
                        float* sm, int b)
{
    float* ws  = sm;                         // NT2*WTST
    float* xws = sm + NT2 * WTST;            // 2 x CH*HH
    float* hb  = xws + 2 * CH * HH;          // 2*HBF
    const int tid = threadIdx.x;
    const int w = tid >> 5, lane = tid & 31;
    const int q = lane >> 3, r = lane & 7;
    const int j0 = w * 32 + r * 4;
    const int myrow = j0 + q;
    const int hoff = (myrow >> 6) * HQ + (myrow & 63);

    // register weights: 4 rows x 52 floats
    unsigned long long w0[RWP / 2], w1[RWP / 2], w2[RWP / 2], w3[RWP / 2];
    {
        const ulonglong2* p0 = (const ulonglong2*)(W_hh + (j0 + 0) * HH + q * 64);
        const ulonglong2* p1 = (const ulonglong2*)(W_hh + (j0 + 1) * HH + q * 64);
        const ulonglong2* p2 = (const ulonglong2*)(W_hh + (j0 + 2) * HH + q * 64);
        const ulonglong2* p3 = (const ulonglong2*)(W_hh + (j0 + 3) * HH + q * 64);
        #pragma unroll
        for (int i = 0; i < RWP / 4; i++) {
            ulonglong2 u;
            u = p0[i]; w0[2 * i] = u.x; w0[2 * i + 1] = u.y;
            u = p1[i]; w1[2 * i] = u.x; w1[2 * i + 1] = u.y;
            u = p2[i]; w2[2 * i] = u.x; w2[2 * i + 1] = u.y;
            u = p3[i]; w3[2 * i] = u.x; w3[2 * i + 1] = u.y;
        }
    }
    // smem weights: 4 rows x 12 floats
    #pragma unroll
    for (int rr = 0; rr < 4; rr++) {
        const ulonglong2* gsrc =
            (const ulonglong2*)(W_hh + (j0 + rr) * HH + q * 64 + RWP);
        ulonglong2* dst = (ulonglong2*)(ws + tid * WTST + rr * SWP);
        #pragma unroll
        for (int i = 0; i < SWP / 4; i++) dst[i] = gsrc[i];
    }

    for (int idx = tid; idx < 2 * HBF; idx += NT2) hb[idx] = 0.0f;

    const float* xg = g_xw + (size_t)b * TT * HH;
    float* hout = g_ht + (size_t)b * TT * HH;
    const uint32_t xw_sbase = (uint32_t)__cvta_generic_to_shared(xws);

    // prologue: stage chunks 0 and 1
    #pragma unroll
    for (int i = 0; i < 8; i++)
        cpa16(xw_sbase + (uint32_t)(tid + i * NT2) * 16,
              (const float4*)xg + tid + i * NT2);
    cpa_commit();
    #pragma unroll
    for (int i = 0; i < 8; i++)
        cpa16(xw_sbase + (uint32_t)(CH * HH / 4 + tid + i * NT2) * 16,
              (const float4*)(xg + CH * HH) + tid + i * NT2);
    cpa_commit();

    int buf = 0;
    float hl = 0.0f;
    const ulonglong2* swp = (const ulonglong2*)(ws + tid * WTST);

    for (int c = 0; c < NCH; c++) {
        if (c >= NCH - 2) { asm volatile("cp.async.wait_group 0;" ::: "memory"); }
        else              { asm volatile("cp.async.wait_group 1;" ::: "memory"); }
        __syncthreads();
        const float* xwc = xws + (c & 1) * (CH * HH);

        for (int s = 0; s < CH; s++) {
            const float xwv = xwc[s * HH + myrow];

            const ulonglong2* h2 = (const ulonglong2*)(hb + buf * HBF + q * HQ);
            unsigned long long a0 = pack2(0.f, 0.f), a1 = a0, a2 = a0, a3 = a0;
            unsigned long long a4 = a0, a5 = a0, a6 = a0, a7 = a0;
            #pragma unroll
            for (int i = 0; i < RWP / 4; i++) {
                ulonglong2 u = h2[i];
                a0 = fma2(w0[2 * i],     u.x, a0);
                a1 = fma2(w0[2 * i + 1], u.y, a1);
                a2 = fma2(w1[2 * i],     u.x, a2);
                a3 = fma2(w1[2 * i + 1], u.y, a3);
                a4 = fma2(w2[2 * i],     u.x, a4);
                a5 = fma2(w2[2 * i + 1], u.y, a5);
                a6 = fma2(w3[2 * i],     u.x, a6);
                a7 = fma2(w3[2 * i + 1], u.y, a7);
            }
            #pragma unroll
            for (int i = 0; i < SWP / 4; i++) {
                ulonglong2 u = h2[RWP / 4 + i];
                ulonglong2 v0 = swp[0 + i];
                ulonglong2 v1 = swp[3 + i];
                ulonglong2 v2 = swp[6 + i];
                ulonglong2 v3 = swp[9 + i];
                a0 = fma2(v0.x, u.x, a0);
                a1 = fma2(v0.y, u.y, a1);
                a2 = fma2(v1.x, u.x, a2);
                a3 = fma2(v1.y, u.y, a3);
                a4 = fma2(v2.x, u.x, a4);
                a5 = fma2(v2.y, u.y, a5);
                a6 = fma2(v3.x, u.x, a6);
                a7 = fma2(v3.y, u.y, a7);
            }
            float p0 = rsum4(a0, a1);
            float p1 = rsum4(a2, a3);
            float p2 = rsum4(a4, a5);
            float p3 = rsum4(a6, a7);
            p0 += __shfl_xor_sync(0xFFFFFFFFu, p0, 8);
            p1 += __shfl_xor_sync(0xFFFFFFFFu, p1, 8);
            p2 += __shfl_xor_sync(0xFFFFFFFFu, p2, 8);
            p3 += __shfl_xor_sync(0xFFFFFFFFu, p3, 8);
            p0 += __shfl_xor_sync(0xFFFFFFFFu, p0, 16);
            p1 += __shfl_xor_sync(0xFFFFFFFFu, p1, 16);
            p2 += __shfl_xor_sync(0xFFFFFFFFu, p2, 16);
            p3 += __shfl_xor_sync(0xFFFFFFFFu, p3, 16);
            const float sd = (q == 0) ? p0 : (q == 1) ? p1 : (q == 2) ? p2 : p3;
            const float hn = fast_tanh(sd + xwv);

            hb[(buf ^ 1) * HBF + hoff] = hn;
            hout[(size_t)(c * CH + s) * HH + myrow] = hn;
            hl = hn;
            __syncthreads();
            buf ^= 1;
        }

        if (tid == 0) st_release(&g_prog[b], (c + 1) * CH);

        if (c + 2 < NCH) {
            const float4* gb = (const float4*)(xg + (size_t)(c + 2) * CH * HH);
            const uint32_t sb = xw_sbase + (uint32_t)((c & 1) * CH * HH) * 4;
            #pragma unroll
            for (int i = 0; i < 8; i++)
                cpa16(sb + (uint32_t)(tid + i * NT2) * 16, gb + tid + i * NT2);
            cpa_commit();
        }
    }
    out[(size_t)BB * TT * II + (size_t)b * HH + myrow] = hl;
    asm volatile("cp.async.wait_group 0;" ::: "memory");
    __syncthreads();
}

// ---------------- MLP worker ----------------------------------------------------
__device__ void mlp_worker(
    const float* __restrict__ x,
    const float* __restrict__ b0, const float* __restrict__ b1,
    const float* __restrict__ b2, const float* __restrict__ b3,
    const float* __restrict__ b4, const float* __restrict__ b5,
    const float* __restrict__ b6, float* __restrict__ out,
    float* sm)
{
    __shared__ int s_blk;
    float* bufA = sm;
    float* bufB = sm + 264 * TOKP;
    const int tid = threadIdx.x;

    for (;;) {
        __syncthreads();
        if (tid == 0) s_blk = atomicAdd(&g_tick, 1);
        __syncthreads();
        const int blk = s_blk;
        if (blk >= 64 * BB) return;
        const int tc = blk >> 6;       // chunk of 64 steps
        const int b = blk & 63;        // chain
        const int need = (tc + 1) * 64;

        if (tid == 0) {
            while (ld_acquire(&g_prog[b]) < need) __nanosleep(128);
        }
        __syncthreads();

        const size_t tok0 = (size_t)b * TT + (size_t)tc * TOKN;

        for (int idx = tid; idx < TOKN * 256; idx += NT2) {
            const int tk = idx >> 8, jj = idx & 255;
            bufA[jj * TOKP + tk] = g_ht[(tok0 + tk) * HH + jj];
        }
        for (int idx = tid; idx < TOKN * 5; idx += NT2) {
            const int tk = idx / 5, i = idx - tk * 5;
            bufA[(256 + i) * TOKP + tk] = x[(tok0 + tk) * XD + II + i];
        }
        __syncthreads();

        mlp_layer<256, 261, 64, true>(bufA, bufB, g_wt + OFF0, b0); __syncthreads();
        mlp_layer<128, 256, 32, true>(bufB, bufA, g_wt + OFF1, b1); __syncthreads();
        mlp_layer< 64, 128, 16, true>(bufA, bufB, g_wt + OFF2, b2); __syncthreads();
        mlp_layer< 32,  64,  8, true>(bufB, bufA, g_wt + OFF3, b3); __syncthreads();
        mlp_layer< 16,  32,  4, true>(bufA, bufB, g_wt + OFF4, b4); __syncthreads();
        mlp_layer<  8,  16,  2, true>(bufB, bufA, g_wt + OFF5, b5); __syncthreads();

        {
            const int o = tid & 7, g0 = tid >> 3;   // g0 in [0,32)
            if (o < 7) {
                #pragma unroll
                for (int g = g0; g < TOKN; g += 32) {
                    float acc = b6[o];
                    #pragma unroll
                    for (int k = 0; k < 8; k++)
                        acc = fmaf(g_wt[OFF6 + k * 7 + o], bufA[k * TOKP + g], acc);
                    out[(tok0 + g) * II + o] = acc;
                }
            }
        }
    }
}

// ---------------- fused kernel --------------------------------------------------
__global__ __launch_bounds__(NT2, 1) void fused_kernel(
    const float* __restrict__ x, const float* __restrict__ W_hh,
    const float* __restrict__ b0, const float* __restrict__ b1,
    const float* __restrict__ b2, const float* __restrict__ b3,
    const float* __restrict__ b4, const float* __restrict__ b5,
    const float* __restrict__ b6, float* __restrict__ out)
{
    extern __shared__ float sm[];
    if (blockIdx.x < NRNN) {
        rnn_cta(W_hh, out, sm, blockIdx.x);
        // chain finished -> join the MLP pool on this SM
        mlp_worker(x, b0, b1, b2, b3, b4, b5, b6, out, sm);
    } else {
        mlp_worker(x, b0, b1, b2, b3, b4, b5, b6, out, sm);
    }
}

// ---------------- xW precompute -------------------------------------------------
__global__ void xw_kernel(const float* __restrict__ x, const float* __restrict__ W_ih,
                          const float* __restrict__ b_ih, const float* __restrict__ b_hh)
{
    const int stride = gridDim.x * blockDim.x;
    for (size_t idx = (size_t)blockIdx.x * blockDim.x + threadIdx.x;
         idx < (size_t)BB * TT * HH; idx += stride) {
        const size_t tok = idx >> 8;
        const int j = (int)(idx & 255);
        const float* xr = x + tok * XD;
        float acc = b_ih[j] + b_hh[j];
        #pragma unroll
        for (int i = 0; i < II; i++) acc = fmaf(xr[i], W_ih[j * II + i], acc);
        g_xw[idx] = acc;
    }
}

// ---------------- prep ----------------------------------------------------------
__global__ void prep_kernel(const float* __restrict__ W0, const float* __restrict__ W1,
                            const float* __restrict__ W2, const float* __restrict__ W3,
                            const float* __restrict__ W4, const float* __restrict__ W5,
                            const float* __restrict__ W6)
{
    if (blockIdx.x == 0) {
        if (threadIdx.x < BB) g_prog[threadIdx.x] = 0;
        if (threadIdx.x == 0) g_tick = 0;
    }
    const float* Ws[7] = {W0, W1, W2, W3, W4, W5, W6};
    const int douts[7] = {256, 128, 64, 32, 16, 8, 7};
    const int dins[7]  = {261, 256, 128, 64, 32, 16, 8};
    int off = 0;
    const int stride = gridDim.x * blockDim.x;
    const int tid0 = blockIdx.x * blockDim.x + threadIdx.x;
    for (int l = 0; l < 7; l++) {
        const int dout = douts[l], din = dins[l], n = dout * din;
        const float* W = Ws[l];
        for (int idx = tid0; idx < n; idx += stride) {
            const int k = idx / dout, o = idx - k * dout;
            g_wt[off + idx] = W[o * din + k];
        }
        off += n;
    }
}

// ---------------- launch --------------------------------------------------------
extern "C" void kernel_launch(void* const* d_in, const int* in_sizes, int n_in,
                              void* d_out, int out_size)
{
    const float* x    = (const float*)d_in[0];
    const float* W_ih = (const float*)d_in[1];
    const float* W_hh = (const float*)d_in[2];
    const float* b_ih = (const float*)d_in[3];
    const float* b_hh = (const float*)d_in[4];
    const float* W[7];
    const float* bb[7];
    for (int i = 0; i < 7; i++) {
        W[i]  = (const float*)d_in[5 + 2 * i];
        bb[i] = (const float*)d_in[6 + 2 * i];
    }
    float* out = (float*)d_out;

    static int inited = 0;
    if (!inited) {
        cudaFuncSetAttribute(fused_kernel,
                             cudaFuncAttributeMaxDynamicSharedMemorySize, FUSED_SMEM_B);
        inited = 1;
    }

    prep_kernel<<<64, 256>>>(W[0], W[1], W[2], W[3], W[4], W[5], W[6]);
    xw_kernel<<<512, 256>>>(x, W_ih, b_ih, b_hh);
    fused_kernel<<<NCTA, NT2, FUSED_SMEM_B>>>(x, W_hh,
                                              bb[0], bb[1], bb[2], bb[3],
                                              bb[4], bb[5], bb[6], out);
}